// round 1
// baseline (speedup 1.0000x reference)
#include <cuda_runtime.h>
#include <cuda_bf16.h>
#include <math.h>

// ---------------------------------------------------------------------------
// ConvTokenEmbedder: char CNN + highway x2 + projection
//   tokens N = 16*256 = 4096
//   char dim 16, max chars 50, filters total 2048, proj 512
// Pipeline:
//   1) conv_kernel: gather char embeddings, 7 conv widths, maxpool+relu -> g_h
//   2) gemm_tn:     p = h @ hw_w0^T + hw_b0            (4096 x 4096)
//   3) highway:     h = g*h + (1-g)*relu(t)
//   4) gemm_tn:     p = h @ hw_w1^T + hw_b1
//   5) highway
//   6) gemm_tn:     out = h @ proj_w^T + proj_b        (4096 x 512)
// ---------------------------------------------------------------------------

#define NTOK   4096
#define NFILT  2048
#define PROJ   512
#define MAXC   50
#define CDIM   16

// Scratch (static device globals; no runtime allocation allowed)
__device__ float g_h[NTOK * NFILT];            // 32 MB
__device__ float g_p[NTOK * 2 * NFILT];        // 64 MB

// ---------------------------------------------------------------------------
// Conv stage
// ---------------------------------------------------------------------------

// max-over-time conv for one filter of compile-time width W.
// xs layout: xs[c*51 + t], t in [0,50). Weight layout: wg[c*W + k].
template <int W>
__device__ __forceinline__ float conv_max(const float* __restrict__ xs,
                                          const float* __restrict__ wg,
                                          float bias) {
    constexpr int NT = 51 - W;     // number of valid time positions
    float acc[NT];
#pragma unroll
    for (int t = 0; t < NT; t++) acc[t] = 0.0f;

#pragma unroll 2
    for (int c = 0; c < CDIM; c++) {
        float wr[W];
#pragma unroll
        for (int k = 0; k < W; k++) wr[k] = wg[c * W + k];
        // x-value register reuse: each xs element feeds up to W accumulators
#pragma unroll
        for (int tp = 0; tp < MAXC; tp++) {
            float xv = xs[c * 51 + tp];
#pragma unroll
            for (int k = 0; k < W; k++) {
                int t = tp - k;                 // compile-time after unroll
                if (t >= 0 && t < NT) acc[t] = fmaf(xv, wr[k], acc[t]);
            }
        }
    }
    float m = acc[0];
#pragma unroll
    for (int t = 1; t < NT; t++) m = fmaxf(m, acc[t]);
    m += bias;
    return fmaxf(m, 0.0f);
}

__global__ __launch_bounds__(256)
void conv_kernel(const int*   __restrict__ chars,
                 const float* __restrict__ emb,
                 const float* __restrict__ w0, const float* __restrict__ b0,
                 const float* __restrict__ w1, const float* __restrict__ b1,
                 const float* __restrict__ w2, const float* __restrict__ b2,
                 const float* __restrict__ w3, const float* __restrict__ b3,
                 const float* __restrict__ w4, const float* __restrict__ b4,
                 const float* __restrict__ w5, const float* __restrict__ b5,
                 const float* __restrict__ w6, const float* __restrict__ b6,
                 float* __restrict__ h) {
    __shared__ float xs[CDIM * 51];
    __shared__ int   chs[MAXC];

    const int n   = blockIdx.x;          // token index
    const int tid = threadIdx.x;

    if (tid < MAXC) chs[tid] = chars[n * MAXC + tid];
    __syncthreads();

    for (int idx = tid; idx < MAXC * CDIM; idx += 256) {
        int t = idx >> 4;
        int c = idx & 15;
        xs[c * 51 + t] = emb[chs[t] * CDIM + c];
    }
    __syncthreads();

    float* hrow = h + (size_t)n * NFILT;

    // i = 0 : filters [0,256). Warp-uniform widths:
    //   warp0 -> w1, warp1 -> w2, warp2-3 -> w3, warp4-7 -> w4
    {
        int f = tid;
        float r;
        if (f < 32)        r = conv_max<1>(xs, w0 + f * (CDIM * 1),        b0[f]);
        else if (f < 64)   r = conv_max<2>(xs, w1 + (f - 32) * (CDIM * 2), b1[f - 32]);
        else if (f < 128)  r = conv_max<3>(xs, w2 + (f - 64) * (CDIM * 3), b2[f - 64]);
        else               r = conv_max<4>(xs, w3 + (f - 128) * (CDIM * 4), b3[f - 128]);
        hrow[f] = r;
    }
    // i = 1 : filters [256,512)  -> width 5
    {
        int f = tid + 256;
        hrow[f] = conv_max<5>(xs, w4 + (f - 256) * (CDIM * 5), b4[f - 256]);
    }
    // i = 2,3 : filters [512,1024) -> width 6
#pragma unroll
    for (int i = 2; i < 4; i++) {
        int f = tid + i * 256;
        hrow[f] = conv_max<6>(xs, w5 + (f - 512) * (CDIM * 6), b5[f - 512]);
    }
    // i = 4..7 : filters [1024,2048) -> width 7
#pragma unroll
    for (int i = 4; i < 8; i++) {
        int f = tid + i * 256;
        hrow[f] = conv_max<7>(xs, w6 + (f - 1024) * (CDIM * 7), b6[f - 1024]);
    }
}

// ---------------------------------------------------------------------------
// SGEMM (TN): C[m,n] = sum_k A[m,K] * B[n,K] + bias[n]
//   A: (M,K) row-major, B: (N,K) row-major, C: (M,N) row-major
//   Tiles: 128x128x16, 256 threads, 8x8 microtile
// ---------------------------------------------------------------------------
#define BM 128
#define BN 128
#define BK 16
#define SPAD 4

__global__ __launch_bounds__(256)
void gemm_tn(const float* __restrict__ A,
             const float* __restrict__ B,
             const float* __restrict__ bias,
             float* __restrict__ C,
             int M, int N, int K) {
    __shared__ float As[BK][BM + SPAD];
    __shared__ float Bs[BK][BN + SPAD];

    const int tid = threadIdx.x;
    const int bm  = blockIdx.y * BM;
    const int bn  = blockIdx.x * BN;

    const int tx = tid & 15;     // 0..15 (n dir)
    const int ty = tid >> 4;     // 0..15 (m dir)

    const int lrow = tid >> 2;          // 0..63
    const int lk4  = (tid & 3) * 4;     // 0,4,8,12

    const float* Aptr = A + (size_t)(bm + lrow) * K + lk4;
    const float* Bptr = B + (size_t)(bn + lrow) * K + lk4;

    float acc[8][8];
#pragma unroll
    for (int i = 0; i < 8; i++)
#pragma unroll
        for (int j = 0; j < 8; j++) acc[i][j] = 0.0f;

    for (int k0 = 0; k0 < K; k0 += BK) {
#pragma unroll
        for (int r = 0; r < 2; r++) {
            float4 va = *(const float4*)(Aptr + (size_t)r * 64 * K + k0);
            As[lk4 + 0][lrow + r * 64] = va.x;
            As[lk4 + 1][lrow + r * 64] = va.y;
            As[lk4 + 2][lrow + r * 64] = va.z;
            As[lk4 + 3][lrow + r * 64] = va.w;
            float4 vb = *(const float4*)(Bptr + (size_t)r * 64 * K + k0);
            Bs[lk4 + 0][lrow + r * 64] = vb.x;
            Bs[lk4 + 1][lrow + r * 64] = vb.y;
            Bs[lk4 + 2][lrow + r * 64] = vb.z;
            Bs[lk4 + 3][lrow + r * 64] = vb.w;
        }
        __syncthreads();

#pragma unroll
        for (int k = 0; k < BK; k++) {
            float a[8], b[8];
            float4 a0 = *(const float4*)&As[k][ty * 8];
            float4 a1 = *(const float4*)&As[k][ty * 8 + 4];
            float4 b0 = *(const float4*)&Bs[k][tx * 8];
            float4 b1 = *(const float4*)&Bs[k][tx * 8 + 4];
            a[0]=a0.x; a[1]=a0.y; a[2]=a0.z; a[3]=a0.w;
            a[4]=a1.x; a[5]=a1.y; a[6]=a1.z; a[7]=a1.w;
            b[0]=b0.x; b[1]=b0.y; b[2]=b0.z; b[3]=b0.w;
            b[4]=b1.x; b[5]=b1.y; b[6]=b1.z; b[7]=b1.w;
#pragma unroll
            for (int i = 0; i < 8; i++)
#pragma unroll
                for (int j = 0; j < 8; j++)
                    acc[i][j] = fmaf(a[i], b[j], acc[i][j]);
        }
        __syncthreads();
    }

    // epilogue: + bias, vectorized stores
#pragma unroll
    for (int i = 0; i < 8; i++) {
        int m = bm + ty * 8 + i;
        float* crow = C + (size_t)m * N + bn + tx * 8;
#pragma unroll
        for (int jq = 0; jq < 2; jq++) {
            int nb = bn + tx * 8 + jq * 4;
            float4 v;
            v.x = acc[i][jq * 4 + 0] + bias[nb + 0];
            v.y = acc[i][jq * 4 + 1] + bias[nb + 1];
            v.z = acc[i][jq * 4 + 2] + bias[nb + 2];
            v.w = acc[i][jq * 4 + 3] + bias[nb + 3];
            *(float4*)(crow + jq * 4) = v;
        }
    }
}

// ---------------------------------------------------------------------------
// Highway combine: h = g*h + (1-g)*relu(t)
//   p: (4096, 4096)  cols [0,2048)=transform, [2048,4096)=gate
// ---------------------------------------------------------------------------
__global__ __launch_bounds__(256)
void highway_kernel(const float* __restrict__ p, float* __restrict__ h) {
    int idx = blockIdx.x * blockDim.x + threadIdx.x;   // one float4 of h
    int total = NTOK * (NFILT / 4);
    if (idx >= total) return;
    int m  = idx / (NFILT / 4);
    int j4 = idx % (NFILT / 4);

    const float4 pt = *(const float4*)(p + (size_t)m * (2 * NFILT) + j4 * 4);
    const float4 pg = *(const float4*)(p + (size_t)m * (2 * NFILT) + NFILT + j4 * 4);
    float4 hv = *(float4*)(h + (size_t)m * NFILT + j4 * 4);

    float g;
    g = 1.0f / (1.0f + expf(-pg.x)); hv.x = g * hv.x + (1.0f - g) * fmaxf(pt.x, 0.0f);
    g = 1.0f / (1.0f + expf(-pg.y)); hv.y = g * hv.y + (1.0f - g) * fmaxf(pt.y, 0.0f);
    g = 1.0f / (1.0f + expf(-pg.z)); hv.z = g * hv.z + (1.0f - g) * fmaxf(pt.z, 0.0f);
    g = 1.0f / (1.0f + expf(-pg.w)); hv.w = g * hv.w + (1.0f - g) * fmaxf(pt.w, 0.0f);

    *(float4*)(h + (size_t)m * NFILT + j4 * 4) = hv;
}

// ---------------------------------------------------------------------------
// Launch
// ---------------------------------------------------------------------------
extern "C" void kernel_launch(void* const* d_in, const int* in_sizes, int n_in,
                              void* d_out, int out_size) {
    const int*   chars  = (const int*)d_in[1];
    const float* emb    = (const float*)d_in[2];
    const float* cw[7], *cb[7];
    for (int i = 0; i < 7; i++) {
        cw[i] = (const float*)d_in[3 + 2 * i];
        cb[i] = (const float*)d_in[4 + 2 * i];
    }
    const float* hw_w0  = (const float*)d_in[17];
    const float* hw_b0  = (const float*)d_in[18];
    const float* hw_w1  = (const float*)d_in[19];
    const float* hw_b1  = (const float*)d_in[20];
    const float* proj_w = (const float*)d_in[21];
    const float* proj_b = (const float*)d_in[22];
    float* out = (float*)d_out;

    static float* hbuf = nullptr;
    static float* pbuf = nullptr;
    if (!hbuf) {
        cudaGetSymbolAddress((void**)&hbuf, g_h);
        cudaGetSymbolAddress((void**)&pbuf, g_p);
    }

    // 1) conv stage
    conv_kernel<<<NTOK, 256>>>(chars, emb,
                               cw[0], cb[0], cw[1], cb[1], cw[2], cb[2],
                               cw[3], cb[3], cw[4], cb[4], cw[5], cb[5],
                               cw[6], cb[6], hbuf);

    dim3 blk(256);
    dim3 grid_hw(2 * NFILT / BN, NTOK / BM);   // (32, 32)
    dim3 grid_pr(PROJ / BN, NTOK / BM);        // (4, 32)
    int hw_blocks = (NTOK * (NFILT / 4) + 255) / 256;

    // 2-3) highway layer 0
    gemm_tn<<<grid_hw, blk>>>(hbuf, hw_w0, hw_b0, pbuf, NTOK, 2 * NFILT, NFILT);
    highway_kernel<<<hw_blocks, blk>>>(pbuf, hbuf);

    // 4-5) highway layer 1
    gemm_tn<<<grid_hw, blk>>>(hbuf, hw_w1, hw_b1, pbuf, NTOK, 2 * NFILT, NFILT);
    highway_kernel<<<hw_blocks, blk>>>(pbuf, hbuf);

    // 6) projection
    gemm_tn<<<grid_pr, blk>>>(hbuf, proj_w, proj_b, out, NTOK, PROJ, NFILT);
}